// round 1
// baseline (speedup 1.0000x reference)
#include <cuda_runtime.h>
#include <cuda_bf16.h>
#include <cstdint>

// Problem constants (shapes are fixed by the dataset)
#define IN_DIM  64
#define HID_DIM 128
#define OUT_DIM 64
#define MAXN    100096   // N=100000 padded

// Scratch: transposed features and aggregation buffer (device globals, no alloc)
__device__ float g_Xt[(size_t)MAXN * IN_DIM];
__device__ float g_agg[(size_t)MAXN * IN_DIM];

// ---------------------------------------------------------------------------
// Kernel 1: transpose inp [64, N] -> Xt [N, 64]  (tiled, smem, conflict-free)
// ---------------------------------------------------------------------------
__global__ void k_transpose(const float* __restrict__ inp, int N) {
    __shared__ float tile[32][33];
    int n0 = blockIdx.x * 32;
    int d0 = blockIdx.y * 32;    // d0 in {0, 32}
    int tx = threadIdx.x;        // 0..31
    int ty = threadIdx.y;        // 0..7

    // Read: coalesced along N
    #pragma unroll
    for (int i = 0; i < 32; i += 8) {
        int d = d0 + ty + i;
        int n = n0 + tx;
        float v = 0.f;
        if (n < N) v = inp[(size_t)d * N + n];
        tile[ty + i][tx] = v;
    }
    __syncthreads();
    // Write: coalesced along feature dim (row of Xt)
    #pragma unroll
    for (int i = 0; i < 32; i += 8) {
        int n = n0 + ty + i;
        int d = d0 + tx;
        if (n < N) g_Xt[(size_t)n * IN_DIM + d] = tile[tx][ty + i];
    }
}

// ---------------------------------------------------------------------------
// Kernel 2: edge aggregation. 16 threads per edge, each does a v4 reduction.
//   agg[dst] += Xt[src]   (64 floats = 16 x float4 per edge)
// ---------------------------------------------------------------------------
__global__ void k_aggregate(const int* __restrict__ src,
                            const int* __restrict__ dst,
                            int E) {
    long long idx = (long long)blockIdx.x * blockDim.x + threadIdx.x;
    long long total = (long long)E * 16;
    if (idx >= total) return;
    int e = (int)(idx >> 4);
    int f = (int)(idx & 15);

    int s = __ldg(&src[e]);
    int d = __ldg(&dst[e]);

    const float4* xt4 = reinterpret_cast<const float4*>(g_Xt);
    float4 v = xt4[(size_t)s * 16 + f];

    float* addr = g_agg + ((size_t)d * 16 + f) * 4;
    asm volatile("red.global.add.v4.f32 [%0], {%1, %2, %3, %4};"
                 :: "l"(addr), "f"(v.x), "f"(v.y), "f"(v.z), "f"(v.w)
                 : "memory");
}

// ---------------------------------------------------------------------------
// Kernel 3: fused MLP.  out[o*N+n] = b2[o] + sum_j relu(b1[j]+W1[j,:]·agg[n,:]) * W2[o,j]
// One thread per node. W1 and W2^T staged in smem (broadcast reads), x/acc in regs.
// ---------------------------------------------------------------------------
__global__ __launch_bounds__(128)
void k_mlp(const float* __restrict__ W1g, const float* __restrict__ b1g,
           const float* __restrict__ W2g, const float* __restrict__ b2g,
           float* __restrict__ out, int N) {
    extern __shared__ float smem[];
    float* W1s = smem;                    // [128][64]
    float* W2t = smem + HID_DIM * IN_DIM; // [128][64]  (transposed W2: W2t[j][o])
    float* b1s = W2t + HID_DIM * OUT_DIM; // [128]
    float* b2s = b1s + HID_DIM;           // [64]

    int tid = threadIdx.x;

    // Stage W1 (direct copy, coalesced)
    for (int i = tid; i < HID_DIM * IN_DIM; i += 128)
        W1s[i] = W1g[i];
    // Stage W2 transposed: W2t[j*64+o] = W2g[o*128+j]
    for (int i = tid; i < HID_DIM * OUT_DIM; i += 128) {
        int j = i >> 6;
        int o = i & 63;
        W2t[i] = W2g[o * HID_DIM + j];
    }
    if (tid < HID_DIM) b1s[tid] = b1g[tid];
    if (tid < OUT_DIM) b2s[tid] = b2g[tid];
    __syncthreads();

    int n = blockIdx.x * 128 + tid;
    bool active = (n < N);

    // Load node features into registers (own-row float4 loads, L2-resident)
    float x[IN_DIM];
    {
        const float4* xg = reinterpret_cast<const float4*>(g_agg + (size_t)(active ? n : 0) * IN_DIM);
        #pragma unroll
        for (int i4 = 0; i4 < 16; i4++) {
            float4 t = xg[i4];
            if (!active) t = make_float4(0.f, 0.f, 0.f, 0.f);
            x[4 * i4 + 0] = t.x; x[4 * i4 + 1] = t.y;
            x[4 * i4 + 2] = t.z; x[4 * i4 + 3] = t.w;
        }
    }

    float acc[OUT_DIM];
    #pragma unroll
    for (int o = 0; o < OUT_DIM; o++) acc[o] = 0.f;

    for (int j = 0; j < HID_DIM; j++) {
        const float4* w1 = reinterpret_cast<const float4*>(W1s + j * IN_DIM);
        float s0 = 0.f, s1 = 0.f, s2 = 0.f, s3 = 0.f;
        #pragma unroll
        for (int i4 = 0; i4 < 16; i4++) {
            float4 w = w1[i4];                   // broadcast LDS.128
            s0 = fmaf(w.x, x[4 * i4 + 0], s0);
            s1 = fmaf(w.y, x[4 * i4 + 1], s1);
            s2 = fmaf(w.z, x[4 * i4 + 2], s2);
            s3 = fmaf(w.w, x[4 * i4 + 3], s3);
        }
        float h = b1s[j] + ((s0 + s1) + (s2 + s3));
        h = fmaxf(h, 0.f);

        const float4* w2 = reinterpret_cast<const float4*>(W2t + j * OUT_DIM);
        #pragma unroll
        for (int o4 = 0; o4 < 16; o4++) {
            float4 w = w2[o4];                   // broadcast LDS.128
            acc[4 * o4 + 0] = fmaf(h, w.x, acc[4 * o4 + 0]);
            acc[4 * o4 + 1] = fmaf(h, w.y, acc[4 * o4 + 1]);
            acc[4 * o4 + 2] = fmaf(h, w.z, acc[4 * o4 + 2]);
            acc[4 * o4 + 3] = fmaf(h, w.w, acc[4 * o4 + 3]);
        }
    }

    if (active) {
        // out is [64, N]: consecutive lanes (n) contiguous -> coalesced
        #pragma unroll
        for (int o = 0; o < OUT_DIM; o++)
            out[(size_t)o * N + n] = acc[o] + b2s[o];
    }
}

// ---------------------------------------------------------------------------
// Launch
// ---------------------------------------------------------------------------
extern "C" void kernel_launch(void* const* d_in, const int* in_sizes, int n_in,
                              void* d_out, int out_size) {
    const float* inp = (const float*)d_in[0];   // [64, N]
    const int*   src = (const int*)d_in[1];     // [E]
    const int*   dst = (const int*)d_in[2];     // [E]
    const float* W1  = (const float*)d_in[3];   // [128, 64]
    const float* b1  = (const float*)d_in[4];   // [128]
    const float* W2  = (const float*)d_in[5];   // [64, 128]
    const float* b2  = (const float*)d_in[6];   // [64]
    float* out = (float*)d_out;                 // [64, N]

    int N = in_sizes[0] / IN_DIM;
    int E = in_sizes[1];

    // Zero the aggregation buffer (graph-capturable async memset)
    void* aggPtr = nullptr;
    cudaGetSymbolAddress(&aggPtr, g_agg);
    cudaMemsetAsync(aggPtr, 0, (size_t)N * IN_DIM * sizeof(float), 0);

    // 1. Transpose
    {
        dim3 grid((N + 31) / 32, 2);
        dim3 block(32, 8);
        k_transpose<<<grid, block>>>(inp, N);
    }

    // 2. Aggregate
    {
        long long total = (long long)E * 16;
        int blocks = (int)((total + 255) / 256);
        k_aggregate<<<blocks, 256>>>(src, dst, E);
    }

    // 3. Fused MLP
    {
        int smemBytes = (HID_DIM * IN_DIM + HID_DIM * OUT_DIM + HID_DIM + OUT_DIM) * sizeof(float);
        cudaFuncSetAttribute(k_mlp, cudaFuncAttributeMaxDynamicSharedMemorySize, smemBytes);
        int blocks = (N + 127) / 128;
        k_mlp<<<blocks, 128, smemBytes>>>(W1, b1, W2, b2, out, N);
    }
}

// round 2
// speedup vs baseline: 1.7151x; 1.7151x over previous
#include <cuda_runtime.h>
#include <cuda_bf16.h>
#include <cstdint>

#define IN_DIM  64
#define HID_DIM 128
#define OUT_DIM 64
#define MAXN    100096
#define MAXE    1600000

typedef unsigned long long ull;

// Scratch (device globals, no alloc)
__device__ __align__(128) float g_Xt [(size_t)MAXN * IN_DIM];
__device__ __align__(128) float g_agg[(size_t)MAXN * IN_DIM];
__device__ int g_deg [MAXN];
__device__ int g_off [MAXN];
__device__ int g_pos [MAXN];
__device__ int g_esrc[MAXE];
__device__ int g_bsum [128];
__device__ int g_bbase[128];

// ---------------------------------------------------------------------------
// Kernel 1: transpose inp [64, N] -> Xt [N, 64]
// ---------------------------------------------------------------------------
__global__ void k_transpose(const float* __restrict__ inp, int N) {
    __shared__ float tile[32][33];
    int n0 = blockIdx.x * 32;
    int d0 = blockIdx.y * 32;
    int tx = threadIdx.x, ty = threadIdx.y;
    #pragma unroll
    for (int i = 0; i < 32; i += 8) {
        int d = d0 + ty + i, n = n0 + tx;
        float v = 0.f;
        if (n < N) v = inp[(size_t)d * N + n];
        tile[ty + i][tx] = v;
    }
    __syncthreads();
    #pragma unroll
    for (int i = 0; i < 32; i += 8) {
        int n = n0 + ty + i, d = d0 + tx;
        if (n < N) g_Xt[(size_t)n * IN_DIM + d] = tile[tx][ty + i];
    }
}

// ---------------------------------------------------------------------------
// CSR build: degree histogram -> block scan -> base scan -> add base -> scatter
// ---------------------------------------------------------------------------
__global__ void k_degree(const int* __restrict__ dst, int E) {
    int e = blockIdx.x * blockDim.x + threadIdx.x;
    if (e < E) atomicAdd(&g_deg[dst[e]], 1);
}

__global__ void k_scan1(int N) {
    __shared__ int sh[1024];
    int tid = threadIdx.x;
    int idx = blockIdx.x * 1024 + tid;
    int val = (idx < N) ? g_deg[idx] : 0;
    sh[tid] = val;
    __syncthreads();
    for (int off = 1; off < 1024; off <<= 1) {
        int t = (tid >= off) ? sh[tid - off] : 0;
        __syncthreads();
        sh[tid] += t;
        __syncthreads();
    }
    if (idx < N) g_off[idx] = sh[tid] - val;      // exclusive within block
    if (tid == 1023) g_bsum[blockIdx.x] = sh[tid];
}

__global__ void k_scan2(int nb) {
    if (threadIdx.x == 0) {
        int run = 0;
        for (int i = 0; i < nb; i++) { g_bbase[i] = run; run += g_bsum[i]; }
    }
}

__global__ void k_scan3(int N) {
    int idx = blockIdx.x * blockDim.x + threadIdx.x;
    if (idx < N) {
        int v = g_off[idx] + g_bbase[idx >> 10];
        g_off[idx] = v;
        g_pos[idx] = v;
    }
}

__global__ void k_scatter(const int* __restrict__ src, const int* __restrict__ dst, int E) {
    int e = blockIdx.x * blockDim.x + threadIdx.x;
    if (e < E) {
        int d = dst[e];
        int p = atomicAdd(&g_pos[d], 1);
        g_esrc[p] = src[e];
    }
}

// ---------------------------------------------------------------------------
// Gather aggregation: one warp per node, lane owns a float2 (64 floats/row).
// Neighbor rows are contiguous 256B reads from L2-resident Xt.
// ---------------------------------------------------------------------------
__global__ __launch_bounds__(256)
void k_gather(int N) {
    int warp = (blockIdx.x * blockDim.x + threadIdx.x) >> 5;
    int lane = threadIdx.x & 31;
    if (warp >= N) return;
    int base = g_off[warp];
    int deg  = g_deg[warp];
    const float2* xt = reinterpret_cast<const float2*>(g_Xt);
    float2 acc = make_float2(0.f, 0.f);
    int k = 0;
    for (; k + 4 <= deg; k += 4) {
        int s0 = __ldg(&g_esrc[base + k + 0]);
        int s1 = __ldg(&g_esrc[base + k + 1]);
        int s2 = __ldg(&g_esrc[base + k + 2]);
        int s3 = __ldg(&g_esrc[base + k + 3]);
        float2 v0 = xt[(size_t)s0 * 32 + lane];
        float2 v1 = xt[(size_t)s1 * 32 + lane];
        float2 v2 = xt[(size_t)s2 * 32 + lane];
        float2 v3 = xt[(size_t)s3 * 32 + lane];
        acc.x += (v0.x + v1.x) + (v2.x + v3.x);
        acc.y += (v0.y + v1.y) + (v2.y + v3.y);
    }
    for (; k < deg; k++) {
        int s = __ldg(&g_esrc[base + k]);
        float2 v = xt[(size_t)s * 32 + lane];
        acc.x += v.x; acc.y += v.y;
    }
    reinterpret_cast<float2*>(g_agg)[(size_t)warp * 32 + lane] = acc;
}

// ---------------------------------------------------------------------------
// Fused MLP with packed f32x2 FMA (sm_103a dual-fp32 pipe via PTX).
// ---------------------------------------------------------------------------
__device__ __forceinline__ ull ffma2(ull a, ull b, ull c) {
    ull d;
    asm("fma.rn.f32x2 %0, %1, %2, %3;" : "=l"(d) : "l"(a), "l"(b), "l"(c));
    return d;
}

__global__ __launch_bounds__(128)
void k_mlp(const float* __restrict__ W1g, const float* __restrict__ b1g,
           const float* __restrict__ W2g, const float* __restrict__ b2g,
           float* __restrict__ out, int N) {
    extern __shared__ float smem[];
    float* W1s = smem;                       // [128][64]
    float* W2t = smem + HID_DIM * IN_DIM;    // [128][64] transposed W2
    float* b1s = W2t + HID_DIM * OUT_DIM;    // [128]
    float* b2s = b1s + HID_DIM;              // [64]

    int tid = threadIdx.x;
    for (int i = tid; i < HID_DIM * IN_DIM; i += 128) W1s[i] = W1g[i];
    for (int i = tid; i < HID_DIM * OUT_DIM; i += 128) {
        int j = i >> 6, o = i & 63;
        W2t[i] = W2g[o * HID_DIM + j];
    }
    if (tid < HID_DIM) b1s[tid] = b1g[tid];
    if (tid < OUT_DIM) b2s[tid] = b2g[tid];
    __syncthreads();

    int n = blockIdx.x * 128 + tid;
    if (n >= N) return;

    // Node features: 32 packed f32 pairs in registers
    ull x2[32];
    {
        const ulonglong2* xg = reinterpret_cast<const ulonglong2*>(g_agg + (size_t)n * IN_DIM);
        #pragma unroll
        for (int i = 0; i < 16; i++) {
            ulonglong2 t = xg[i];
            x2[2 * i] = t.x; x2[2 * i + 1] = t.y;
        }
    }

    // Accumulators init with b2 (packed pairs)
    ull acc2[32];
    {
        const ulonglong2* bp = reinterpret_cast<const ulonglong2*>(b2s);
        #pragma unroll
        for (int i = 0; i < 16; i++) {
            ulonglong2 t = bp[i];
            acc2[2 * i] = t.x; acc2[2 * i + 1] = t.y;
        }
    }

    for (int j = 0; j < HID_DIM; j++) {
        const ulonglong2* w1 = reinterpret_cast<const ulonglong2*>(W1s + j * IN_DIM);
        ull sA = 0ull, sB = 0ull;   // packed (0.f, 0.f)
        #pragma unroll
        for (int i = 0; i < 16; i++) {
            ulonglong2 w = w1[i];
            sA = ffma2(w.x, x2[2 * i], sA);
            sB = ffma2(w.y, x2[2 * i + 1], sB);
        }
        float2 a = *reinterpret_cast<float2*>(&sA);
        float2 b = *reinterpret_cast<float2*>(&sB);
        float h = b1s[j] + ((a.x + a.y) + (b.x + b.y));
        h = fmaxf(h, 0.f);
        ull h2;
        { float2 hh = make_float2(h, h); h2 = *reinterpret_cast<ull*>(&hh); }

        const ulonglong2* w2 = reinterpret_cast<const ulonglong2*>(W2t + j * OUT_DIM);
        #pragma unroll
        for (int o = 0; o < 16; o++) {
            ulonglong2 w = w2[o];
            acc2[2 * o]     = ffma2(h2, w.x, acc2[2 * o]);
            acc2[2 * o + 1] = ffma2(h2, w.y, acc2[2 * o + 1]);
        }
    }

    #pragma unroll
    for (int o = 0; o < 32; o++) {
        float2 v = *reinterpret_cast<float2*>(&acc2[o]);
        out[(size_t)(2 * o) * N + n]     = v.x;
        out[(size_t)(2 * o + 1) * N + n] = v.y;
    }
}

// ---------------------------------------------------------------------------
// Launch
// ---------------------------------------------------------------------------
extern "C" void kernel_launch(void* const* d_in, const int* in_sizes, int n_in,
                              void* d_out, int out_size) {
    const float* inp = (const float*)d_in[0];
    const int*   src = (const int*)d_in[1];
    const int*   dst = (const int*)d_in[2];
    const float* W1  = (const float*)d_in[3];
    const float* b1  = (const float*)d_in[4];
    const float* W2  = (const float*)d_in[5];
    const float* b2  = (const float*)d_in[6];
    float* out = (float*)d_out;

    int N = in_sizes[0] / IN_DIM;
    int E = in_sizes[1];

    // Zero degree counters
    void* degPtr = nullptr;
    cudaGetSymbolAddress(&degPtr, g_deg);
    cudaMemsetAsync(degPtr, 0, (size_t)N * sizeof(int), 0);

    // 1. Transpose features
    {
        dim3 grid((N + 31) / 32, 2);
        dim3 block(32, 8);
        k_transpose<<<grid, block>>>(inp, N);
    }

    // 2. CSR build
    int eBlocks = (E + 255) / 256;
    k_degree<<<eBlocks, 256>>>(dst, E);
    int nb = (N + 1023) / 1024;
    k_scan1<<<nb, 1024>>>(N);
    k_scan2<<<1, 32>>>(nb);
    k_scan3<<<(N + 255) / 256, 256>>>(N);
    k_scatter<<<eBlocks, 256>>>(src, dst, E);

    // 3. Gather aggregation (warp per node)
    {
        int warpsNeeded = N;
        int blocks = (warpsNeeded * 32 + 255) / 256;
        k_gather<<<blocks, 256>>>(N);
    }

    // 4. Fused MLP (packed f32x2)
    {
        int smemBytes = (HID_DIM * IN_DIM + HID_DIM * OUT_DIM + HID_DIM + OUT_DIM) * sizeof(float);
        cudaFuncSetAttribute(k_mlp, cudaFuncAttributeMaxDynamicSharedMemorySize, smemBytes);
        int blocks = (N + 127) / 128;
        k_mlp<<<blocks, 128, smemBytes>>>(W1, b1, W2, b2, out, N);
    }
}

// round 3
// speedup vs baseline: 1.7674x; 1.0305x over previous
#include <cuda_runtime.h>
#include <cuda_bf16.h>
#include <cstdint>

#define IN_DIM  64
#define HID_DIM 128
#define OUT_DIM 64
#define MAXN    100096
#define MAXE    1600000

typedef unsigned long long ull;

// Scratch (device globals, no alloc)
__device__ __align__(128) float g_Xt [(size_t)MAXN * IN_DIM];
__device__ __align__(128) float g_agg[(size_t)MAXN * IN_DIM];
__device__ int g_deg [MAXN];
__device__ int g_off [MAXN];   // block-local exclusive offsets
__device__ int g_pos [MAXN];   // running counters (start = local offset)
__device__ int g_esrc[MAXE];
__device__ int g_bsum [128];
__device__ int g_bbase[128];   // per-1024-block base offsets

// ---------------------------------------------------------------------------
// Kernel 0: transpose inp [64, N] -> Xt [N, 64]; also zeros g_deg
// ---------------------------------------------------------------------------
__global__ void k_transpose(const float* __restrict__ inp, int N) {
    __shared__ float tile[32][33];
    int n0 = blockIdx.x * 32;
    int d0 = blockIdx.y * 32;
    int tx = threadIdx.x, ty = threadIdx.y;

    if (blockIdx.y == 0 && ty == 0) {
        int n = n0 + tx;
        if (n < N) g_deg[n] = 0;
    }

    #pragma unroll
    for (int i = 0; i < 32; i += 8) {
        int d = d0 + ty + i, n = n0 + tx;
        float v = 0.f;
        if (n < N) v = inp[(size_t)d * N + n];
        tile[ty + i][tx] = v;
    }
    __syncthreads();
    #pragma unroll
    for (int i = 0; i < 32; i += 8) {
        int n = n0 + ty + i, d = d0 + tx;
        if (n < N) g_Xt[(size_t)n * IN_DIM + d] = tile[tx][ty + i];
    }
}

// ---------------------------------------------------------------------------
// CSR build
// ---------------------------------------------------------------------------
__global__ void k_degree(const int* __restrict__ dst, int E) {
    int e = blockIdx.x * blockDim.x + threadIdx.x;
    if (e < E) atomicAdd(&g_deg[dst[e]], 1);
}

__global__ void k_scan1(int N) {
    __shared__ int sh[1024];
    int tid = threadIdx.x;
    int idx = blockIdx.x * 1024 + tid;
    int val = (idx < N) ? g_deg[idx] : 0;
    sh[tid] = val;
    __syncthreads();
    for (int off = 1; off < 1024; off <<= 1) {
        int t = (tid >= off) ? sh[tid - off] : 0;
        __syncthreads();
        sh[tid] += t;
        __syncthreads();
    }
    if (idx < N) {
        int ex = sh[tid] - val;        // exclusive within block
        g_off[idx] = ex;
        g_pos[idx] = ex;
    }
    if (tid == 1023) g_bsum[blockIdx.x] = sh[tid];
}

// Parallel scan of <=128 block sums (exclusive)
__global__ void k_scan2(int nb) {
    __shared__ int sh[128];
    int tid = threadIdx.x;
    int v = (tid < nb) ? g_bsum[tid] : 0;
    sh[tid] = v;
    __syncthreads();
    for (int off = 1; off < 128; off <<= 1) {
        int t = (tid >= off) ? sh[tid - off] : 0;
        __syncthreads();
        sh[tid] += t;
        __syncthreads();
    }
    if (tid < nb) g_bbase[tid] = sh[tid] - v;
}

__global__ void k_scatter(const int* __restrict__ src, const int* __restrict__ dst, int E) {
    int e = blockIdx.x * blockDim.x + threadIdx.x;
    if (e < E) {
        int d = dst[e];
        int p = atomicAdd(&g_pos[d], 1) + g_bbase[d >> 10];
        g_esrc[p] = src[e];
    }
}

// ---------------------------------------------------------------------------
// Gather aggregation: 16 lanes per node (float4 per lane, 2 nodes per warp).
// Indices batched 8-at-a-time before 8 independent row loads (MLP ~8).
// ---------------------------------------------------------------------------
__global__ __launch_bounds__(256)
void k_gather(int N) {
    int t = blockIdx.x * 256 + threadIdx.x;
    int node = t >> 4;
    if (node >= N) return;
    int fl = t & 15;
    int base = g_off[node] + g_bbase[node >> 10];
    int deg  = g_deg[node];
    const float4* xt = reinterpret_cast<const float4*>(g_Xt);

    float4 accA = make_float4(0.f, 0.f, 0.f, 0.f);
    float4 accB = make_float4(0.f, 0.f, 0.f, 0.f);
    int k = 0;
    for (; k + 8 <= deg; k += 8) {
        int s[8];
        #pragma unroll
        for (int i = 0; i < 8; i++) s[i] = __ldg(&g_esrc[base + k + i]);
        float4 v[8];
        #pragma unroll
        for (int i = 0; i < 8; i++) v[i] = xt[(size_t)s[i] * 16 + fl];
        #pragma unroll
        for (int i = 0; i < 8; i += 2) {
            accA.x += v[i].x;   accA.y += v[i].y;
            accA.z += v[i].z;   accA.w += v[i].w;
            accB.x += v[i+1].x; accB.y += v[i+1].y;
            accB.z += v[i+1].z; accB.w += v[i+1].w;
        }
    }
    for (; k < deg; k++) {
        int s = __ldg(&g_esrc[base + k]);
        float4 v = xt[(size_t)s * 16 + fl];
        accA.x += v.x; accA.y += v.y; accA.z += v.z; accA.w += v.w;
    }
    float4 acc = make_float4(accA.x + accB.x, accA.y + accB.y,
                             accA.z + accB.z, accA.w + accB.w);
    reinterpret_cast<float4*>(g_agg)[(size_t)node * 16 + fl] = acc;
}

// ---------------------------------------------------------------------------
// Fused MLP with packed f32x2 FMA (pipe-bound; unchanged structure)
// ---------------------------------------------------------------------------
__device__ __forceinline__ ull ffma2(ull a, ull b, ull c) {
    ull d;
    asm("fma.rn.f32x2 %0, %1, %2, %3;" : "=l"(d) : "l"(a), "l"(b), "l"(c));
    return d;
}

__global__ __launch_bounds__(128)
void k_mlp(const float* __restrict__ W1g, const float* __restrict__ b1g,
           const float* __restrict__ W2g, const float* __restrict__ b2g,
           float* __restrict__ out, int N) {
    extern __shared__ float smem[];
    float* W1s = smem;                       // [128][64]
    float* W2t = smem + HID_DIM * IN_DIM;    // [128][64] transposed W2
    float* b1s = W2t + HID_DIM * OUT_DIM;    // [128]
    float* b2s = b1s + HID_DIM;              // [64]

    int tid = threadIdx.x;
    for (int i = tid; i < HID_DIM * IN_DIM; i += 128) W1s[i] = W1g[i];
    for (int i = tid; i < HID_DIM * OUT_DIM; i += 128) {
        int j = i >> 6, o = i & 63;
        W2t[i] = W2g[o * HID_DIM + j];
    }
    if (tid < HID_DIM) b1s[tid] = b1g[tid];
    if (tid < OUT_DIM) b2s[tid] = b2g[tid];
    __syncthreads();

    int n = blockIdx.x * 128 + tid;
    if (n >= N) return;

    ull x2[32];
    {
        const ulonglong2* xg = reinterpret_cast<const ulonglong2*>(g_agg + (size_t)n * IN_DIM);
        #pragma unroll
        for (int i = 0; i < 16; i++) {
            ulonglong2 t = xg[i];
            x2[2 * i] = t.x; x2[2 * i + 1] = t.y;
        }
    }

    ull acc2[32];
    {
        const ulonglong2* bp = reinterpret_cast<const ulonglong2*>(b2s);
        #pragma unroll
        for (int i = 0; i < 16; i++) {
            ulonglong2 t = bp[i];
            acc2[2 * i] = t.x; acc2[2 * i + 1] = t.y;
        }
    }

    for (int j = 0; j < HID_DIM; j++) {
        const ulonglong2* w1 = reinterpret_cast<const ulonglong2*>(W1s + j * IN_DIM);
        ull sA = 0ull, sB = 0ull;
        #pragma unroll
        for (int i = 0; i < 16; i++) {
            ulonglong2 w = w1[i];
            sA = ffma2(w.x, x2[2 * i], sA);
            sB = ffma2(w.y, x2[2 * i + 1], sB);
        }
        float2 a = *reinterpret_cast<float2*>(&sA);
        float2 b = *reinterpret_cast<float2*>(&sB);
        float h = b1s[j] + ((a.x + a.y) + (b.x + b.y));
        h = fmaxf(h, 0.f);
        ull h2;
        { float2 hh = make_float2(h, h); h2 = *reinterpret_cast<ull*>(&hh); }

        const ulonglong2* w2 = reinterpret_cast<const ulonglong2*>(W2t + j * OUT_DIM);
        #pragma unroll
        for (int o = 0; o < 16; o++) {
            ulonglong2 w = w2[o];
            acc2[2 * o]     = ffma2(h2, w.x, acc2[2 * o]);
            acc2[2 * o + 1] = ffma2(h2, w.y, acc2[2 * o + 1]);
        }
    }

    #pragma unroll
    for (int o = 0; o < 32; o++) {
        float2 v = *reinterpret_cast<float2*>(&acc2[o]);
        out[(size_t)(2 * o) * N + n]     = v.x;
        out[(size_t)(2 * o + 1) * N + n] = v.y;
    }
}

// ---------------------------------------------------------------------------
// Launch: k_gather is the 6th launch (index 5) -> it gets the ncu capture.
// ---------------------------------------------------------------------------
extern "C" void kernel_launch(void* const* d_in, const int* in_sizes, int n_in,
                              void* d_out, int out_size) {
    const float* inp = (const float*)d_in[0];
    const int*   src = (const int*)d_in[1];
    const int*   dst = (const int*)d_in[2];
    const float* W1  = (const float*)d_in[3];
    const float* b1  = (const float*)d_in[4];
    const float* W2  = (const float*)d_in[5];
    const float* b2  = (const float*)d_in[6];
    float* out = (float*)d_out;

    int N = in_sizes[0] / IN_DIM;
    int E = in_sizes[1];

    // 0. Transpose (+ zero degree counters)
    {
        dim3 grid((N + 31) / 32, 2);
        dim3 block(32, 8);
        k_transpose<<<grid, block>>>(inp, N);
    }

    // 1-4. CSR build
    int eBlocks = (E + 255) / 256;
    k_degree<<<eBlocks, 256>>>(dst, E);
    int nb = (N + 1023) / 1024;
    k_scan1<<<nb, 1024>>>(N);
    k_scan2<<<1, 128>>>(nb);
    k_scatter<<<eBlocks, 256>>>(src, dst, E);

    // 5. Gather aggregation (16 lanes per node)  <-- ncu capture slot
    {
        long long threads = (long long)N * 16;
        int blocks = (int)((threads + 255) / 256);
        k_gather<<<blocks, 256>>>(N);
    }

    // 6. Fused MLP
    {
        int smemBytes = (HID_DIM * IN_DIM + HID_DIM * OUT_DIM + HID_DIM + OUT_DIM) * sizeof(float);
        cudaFuncSetAttribute(k_mlp, cudaFuncAttributeMaxDynamicSharedMemorySize, smemBytes);
        int blocks = (N + 127) / 128;
        k_mlp<<<blocks, 128, smemBytes>>>(W1, b1, W2, b2, out, N);
    }
}

// round 4
// speedup vs baseline: 1.9609x; 1.1095x over previous
#include <cuda_runtime.h>
#include <cuda_bf16.h>
#include <cstdint>

#define IN_DIM  64
#define HID_DIM 128
#define OUT_DIM 64
#define MAXN    100096
#define MAXE    1600000
#define NPB     64          // nodes per block in fused kernel
#define SROW    72          // padded smem row stride (floats), 16B-aligned

typedef unsigned long long ull;

// Scratch (device globals, no alloc)
__device__ __align__(128) float g_Xt [(size_t)MAXN * IN_DIM];
__device__ __align__(128) float g_W2t[HID_DIM * OUT_DIM];   // W2 transposed [j][o]
__device__ int g_deg [MAXN];
__device__ int g_off [MAXN];
__device__ int g_pos [MAXN];
__device__ int g_esrc[MAXE];
__device__ int g_cnt;

// ---------------------------------------------------------------------------
// Kernel 0: transpose inp [64,N] -> Xt [N,64]; zero g_deg and g_cnt
// ---------------------------------------------------------------------------
__global__ void k_prep(const float* __restrict__ inp, int N) {
    __shared__ float tile[32][33];
    int n0 = blockIdx.x * 32;
    int d0 = blockIdx.y * 32;
    int tx = threadIdx.x, ty = threadIdx.y;

    if (blockIdx.y == 0 && ty == 0) {
        int n = n0 + tx;
        if (n < N) g_deg[n] = 0;
        if (blockIdx.x == 0 && tx == 0) g_cnt = 0;
    }

    #pragma unroll
    for (int i = 0; i < 32; i += 8) {
        int d = d0 + ty + i, n = n0 + tx;
        float v = 0.f;
        if (n < N) v = inp[(size_t)d * N + n];
        tile[ty + i][tx] = v;
    }
    __syncthreads();
    #pragma unroll
    for (int i = 0; i < 32; i += 8) {
        int n = n0 + ty + i, d = d0 + tx;
        if (n < N) g_Xt[(size_t)n * IN_DIM + d] = tile[tx][ty + i];
    }
}

// ---------------------------------------------------------------------------
// Kernel 1: degree histogram; block 0 also builds W2t (8192 elems, trivial)
// ---------------------------------------------------------------------------
__global__ void k_degree(const int* __restrict__ dst, int E,
                         const float* __restrict__ W2g) {
    if (blockIdx.x == 0) {
        for (int i = threadIdx.x; i < HID_DIM * OUT_DIM; i += blockDim.x) {
            int j = i >> 6, o = i & 63;
            g_W2t[i] = W2g[o * HID_DIM + j];
        }
    }
    int e = blockIdx.x * blockDim.x + threadIdx.x;
    if (e < E) atomicAdd(&g_deg[dst[e]], 1);
}

// ---------------------------------------------------------------------------
// Kernel 2: CSR offset alloc via warp-aggregated atomic bump (order-free)
// ---------------------------------------------------------------------------
__global__ void k_alloc(int N) {
    int idx = blockIdx.x * blockDim.x + threadIdx.x;
    int lane = threadIdx.x & 31;
    int d = (idx < N) ? g_deg[idx] : 0;
    // inclusive warp scan
    int pref = d;
    #pragma unroll
    for (int off = 1; off < 32; off <<= 1) {
        int t = __shfl_up_sync(0xFFFFFFFFu, pref, off);
        if (lane >= off) pref += t;
    }
    int total = __shfl_sync(0xFFFFFFFFu, pref, 31);
    int base = 0;
    if (lane == 31) base = atomicAdd(&g_cnt, total);
    base = __shfl_sync(0xFFFFFFFFu, base, 31);
    if (idx < N) {
        int o = base + pref - d;
        g_off[idx] = o;
        g_pos[idx] = o;
    }
}

// ---------------------------------------------------------------------------
// Kernel 3: scatter edge sources into CSR buckets
// ---------------------------------------------------------------------------
__global__ void k_scatter(const int* __restrict__ src, const int* __restrict__ dst, int E) {
    int e = blockIdx.x * blockDim.x + threadIdx.x;
    if (e < E) {
        int p = atomicAdd(&g_pos[dst[e]], 1);
        g_esrc[p] = src[e];
    }
}

// ---------------------------------------------------------------------------
// Kernel 4: FUSED gather + MLP.  Block handles 64 nodes.
//   smem: W1s[128][64] | W2t[128][64] | b1[128] | b2[64] | Xs[64][72] | Hs[64][72]
//   Phase G: gather neighbor sums into Xs (16 lanes/node, float4/lane)
//   Phase A(half): h[j] = relu(b1+W1.x) for 64 j -> Hs
//   Phase B(half): acc[o] += W2t[j][o]*h[j]   (acc in regs, 16 o/thread)
// ---------------------------------------------------------------------------
__device__ __forceinline__ ull ffma2(ull a, ull b, ull c) {
    ull d;
    asm("fma.rn.f32x2 %0, %1, %2, %3;" : "=l"(d) : "l"(a), "l"(b), "l"(c));
    return d;
}

#define OFF_W1  0
#define OFF_W2  (HID_DIM * IN_DIM)                   // 8192
#define OFF_B1  (OFF_W2 + HID_DIM * OUT_DIM)         // 16384
#define OFF_B2  (OFF_B1 + HID_DIM)                   // 16512
#define OFF_XS  (OFF_B2 + OUT_DIM)                   // 16576
#define OFF_HS  (OFF_XS + NPB * SROW)                // 21184
#define SMEM_FLOATS (OFF_HS + NPB * SROW)            // 25792 -> 103168 B

__global__ __launch_bounds__(256, 2)
void k_fused(const float* __restrict__ W1g, const float* __restrict__ b1g,
             const float* __restrict__ b2g, float* __restrict__ out, int N) {
    extern __shared__ float sm[];
    float* W1s = sm + OFF_W1;
    float* W2t = sm + OFF_W2;
    float* b1s = sm + OFF_B1;
    float* b2s = sm + OFF_B2;
    float* Xs  = sm + OFF_XS;
    float* Hs  = sm + OFF_HS;

    int t = threadIdx.x;
    int nodeBase = blockIdx.x * NPB;

    // ---- stage weights (coalesced; W2t pre-transposed in gmem) ----
    {
        const float4* w1 = reinterpret_cast<const float4*>(W1g);
        const float4* w2 = reinterpret_cast<const float4*>(g_W2t);
        float4* w1d = reinterpret_cast<float4*>(W1s);
        float4* w2d = reinterpret_cast<float4*>(W2t);
        #pragma unroll
        for (int i = 0; i < 8; i++) w1d[t + 256 * i] = w1[t + 256 * i];
        #pragma unroll
        for (int i = 0; i < 8; i++) w2d[t + 256 * i] = w2[t + 256 * i];
        if (t < HID_DIM) b1s[t] = b1g[t];
        if (t < OUT_DIM) b2s[t] = b2g[t];
    }

    // ---- Phase G: gather (4 passes x 16 nodes, 16 lanes/node) ----
    {
        int fl = t & 15;
        const float4* xt = reinterpret_cast<const float4*>(g_Xt);
        #pragma unroll
        for (int p = 0; p < 4; p++) {
            int nl = p * 16 + (t >> 4);
            int node = nodeBase + nl;
            int base = 0, deg = 0;
            if (node < N) { base = g_off[node]; deg = g_deg[node]; }
            float4 accA = make_float4(0.f, 0.f, 0.f, 0.f);
            float4 accB = make_float4(0.f, 0.f, 0.f, 0.f);
            int k = 0;
            for (; k + 8 <= deg; k += 8) {
                int s[8];
                #pragma unroll
                for (int i = 0; i < 8; i++) s[i] = __ldg(&g_esrc[base + k + i]);
                float4 v[8];
                #pragma unroll
                for (int i = 0; i < 8; i++) v[i] = xt[(size_t)s[i] * 16 + fl];
                #pragma unroll
                for (int i = 0; i < 8; i += 2) {
                    accA.x += v[i].x;   accA.y += v[i].y;
                    accA.z += v[i].z;   accA.w += v[i].w;
                    accB.x += v[i+1].x; accB.y += v[i+1].y;
                    accB.z += v[i+1].z; accB.w += v[i+1].w;
                }
            }
            for (; k < deg; k++) {
                int s = __ldg(&g_esrc[base + k]);
                float4 v = xt[(size_t)s * 16 + fl];
                accA.x += v.x; accA.y += v.y; accA.z += v.z; accA.w += v.w;
            }
            float4 acc = make_float4(accA.x + accB.x, accA.y + accB.y,
                                     accA.z + accB.z, accA.w + accB.w);
            *reinterpret_cast<float4*>(Xs + nl * SROW + fl * 4) = acc;
        }
    }
    __syncthreads();

    // ---- MLP: x regs persistent, acc regs persistent; j in two halves ----
    int n  = t & 63;           // node-local
    int g4 = t >> 6;           // 0..3 : j-group (A) / o-group (B)

    ull x2[32];
    {
        const ulonglong2* xr = reinterpret_cast<const ulonglong2*>(Xs + n * SROW);
        #pragma unroll
        for (int i = 0; i < 16; i++) {
            ulonglong2 v = xr[i];
            x2[2 * i] = v.x; x2[2 * i + 1] = v.y;
        }
    }

    ull acc2[8];
    {
        const ulonglong2* bp = reinterpret_cast<const ulonglong2*>(b2s + g4 * 16);
        #pragma unroll
        for (int q = 0; q < 4; q++) {
            ulonglong2 v = bp[q];
            acc2[2 * q] = v.x; acc2[2 * q + 1] = v.y;
        }
    }

    #pragma unroll
    for (int half = 0; half < 2; half++) {
        // Phase A: 16 hidden units per thread
        #pragma unroll 4
        for (int jj = 0; jj < 16; jj++) {
            int jl = g4 * 16 + jj;            // local j (0..63)
            int j  = half * 64 + jl;
            const ulonglong2* w = reinterpret_cast<const ulonglong2*>(W1s + j * IN_DIM);
            ull sA = 0ull, sB = 0ull;
            #pragma unroll
            for (int i = 0; i < 16; i++) {
                ulonglong2 ww = w[i];
                sA = ffma2(ww.x, x2[2 * i], sA);
                sB = ffma2(ww.y, x2[2 * i + 1], sB);
            }
            float2 a = *reinterpret_cast<float2*>(&sA);
            float2 b = *reinterpret_cast<float2*>(&sB);
            float h = b1s[j] + ((a.x + a.y) + (b.x + b.y));
            Hs[jl * SROW + n] = fmaxf(h, 0.f);
        }
        __syncthreads();

        // Phase B: 16 outputs per thread, accumulate over 64 local j
        #pragma unroll 8
        for (int jl = 0; jl < 64; jl++) {
            float h = Hs[jl * SROW + n];
            float2 hh = make_float2(h, h);
            ull h2 = *reinterpret_cast<ull*>(&hh);
            int j = half * 64 + jl;
            const ulonglong2* w = reinterpret_cast<const ulonglong2*>(W2t + j * OUT_DIM + g4 * 16);
            #pragma unroll
            for (int q = 0; q < 4; q++) {
                ulonglong2 ww = w[q];
                acc2[2 * q]     = ffma2(h2, ww.x, acc2[2 * q]);
                acc2[2 * q + 1] = ffma2(h2, ww.y, acc2[2 * q + 1]);
            }
        }
        __syncthreads();
    }

    // ---- write out [64, N], coalesced over n ----
    int node = nodeBase + n;
    if (node < N) {
        #pragma unroll
        for (int q = 0; q < 8; q++) {
            float2 v = *reinterpret_cast<float2*>(&acc2[q]);
            int o = g4 * 16 + 2 * q;
            out[(size_t)o * N + node]       = v.x;
            out[(size_t)(o + 1) * N + node] = v.y;
        }
    }
}

// ---------------------------------------------------------------------------
// Launch (5 kernels)
// ---------------------------------------------------------------------------
extern "C" void kernel_launch(void* const* d_in, const int* in_sizes, int n_in,
                              void* d_out, int out_size) {
    const float* inp = (const float*)d_in[0];
    const int*   src = (const int*)d_in[1];
    const int*   dst = (const int*)d_in[2];
    const float* W1  = (const float*)d_in[3];
    const float* b1  = (const float*)d_in[4];
    const float* W2  = (const float*)d_in[5];
    const float* b2  = (const float*)d_in[6];
    float* out = (float*)d_out;

    int N = in_sizes[0] / IN_DIM;
    int E = in_sizes[1];

    // 0. Transpose + zero counters
    {
        dim3 grid((N + 31) / 32, 2);
        dim3 block(32, 8);
        k_prep<<<grid, block>>>(inp, N);
    }
    // 1. Degree (+ W2 transpose piggyback)
    int eBlocks = (E + 255) / 256;
    k_degree<<<eBlocks, 256>>>(dst, E, W2);
    // 2. Offset alloc
    k_alloc<<<(N + 255) / 256, 256>>>(N);
    // 3. Scatter
    k_scatter<<<eBlocks, 256>>>(src, dst, E);
    // 4. Fused gather + MLP
    {
        int smemBytes = SMEM_FLOATS * sizeof(float);
        cudaFuncSetAttribute(k_fused, cudaFuncAttributeMaxDynamicSharedMemorySize, smemBytes);
        int blocks = (N + NPB - 1) / NPB;
        k_fused<<<blocks, 256, smemBytes>>>(W1, b1, b2, out, N);
    }
}